// round 5
// baseline (speedup 1.0000x reference)
#include <cuda_runtime.h>

// LDR toeplitz-displacement layer via FFT with 2-term real packing.
//   Hf = fft(D*H); Gf = fft(G); Xf = ifft(conj(D)*x)
//   t = D*fft(Hf.Xf) is REAL => pack two terms: z = u1 + i*u2,
//   W = fft(D.fft(z)) = Tf1 + i*Tf2 (Tf Hermitian), unpack via reversed read.
//   out = Re(ifft(sum Gf.Tf)) / (2N).
// MAIN-KERNEL FFT (new): four-step 4096 = 64 x 64.
//   Layout L: thread (w,g=sub-group,s=lane&7), reg j holds index
//             n = P + 64*s + 512*j,  P = 4w+g.
//   FFT64 = FFT8(regs) -> tw W64^{s*m}(regs) -> 8x8 shfl transpose -> FFT8(regs)
//   FFT4096 = FFT64 -> mid twiddle W4096^{P*u} -> ONE smem transpose (stride-68,
//             <=2-way conflicts, 1 barrier) -> FFT64.  Layout maps L -> L.
// Per FFT: 1 barrier + 1 exchange (was 3+3).

#define NN    4096
#define NT    512
#define CIN   4
#define COUT  4
#define RANK  4
#define BATCH 32

// ---- prep kernel (unchanged Stockham radix-8) ----
#define PIDX(i) ((i) + ((i) >> 3))
#define NPAD   4608
#define WSIZE  512

// ---- main kernel smem: two 64x68 float2 transpose buffers ----
#define TSTRIDE 68
#define TBUF    (64 * TSTRIDE)                       // 4352 float2
#define MAIN_SMEM (2 * TBUF * (int)sizeof(float2))   // 69632 B

__device__ float2 g_Hf[CIN*COUT*RANK][NN];   // 2 MB
__device__ float2 g_Gf[CIN*COUT*RANK][NN];   // 2 MB
__device__ float2 g_Xf[CIN*BATCH][NN];       // 4 MB

__device__ __forceinline__ float2 cmul(float2 a, float2 b) {
    return make_float2(a.x*b.x - a.y*b.y, a.x*b.y + a.y*b.x);
}
__device__ __forceinline__ float2 cadd(float2 a, float2 b) { return make_float2(a.x+b.x, a.y+b.y); }
__device__ __forceinline__ float2 csub(float2 a, float2 b) { return make_float2(a.x-b.x, a.y-b.y); }

// 8-pt DFT in registers, natural order in/out. INV=0: W8 = e^{-2pi i/8}.
template<int INV>
__device__ __forceinline__ void bf8(float2 v[8]) {
    const float C = 0.70710678118654752440f;
    float2 e0,e1,e2,e3,o0,o1,o2,o3;
    {
        float2 t0 = cadd(v[0], v[4]);
        float2 t1 = csub(v[0], v[4]);
        float2 t2 = cadd(v[2], v[6]);
        float2 d  = csub(v[2], v[6]);
        float2 t3 = INV ? make_float2(-d.y, d.x) : make_float2(d.y, -d.x);
        e0 = cadd(t0,t2); e1 = cadd(t1,t3); e2 = csub(t0,t2); e3 = csub(t1,t3);
    }
    {
        float2 t0 = cadd(v[1], v[5]);
        float2 t1 = csub(v[1], v[5]);
        float2 t2 = cadd(v[3], v[7]);
        float2 d  = csub(v[3], v[7]);
        float2 t3 = INV ? make_float2(-d.y, d.x) : make_float2(d.y, -d.x);
        o0 = cadd(t0,t2); o1 = cadd(t1,t3); o2 = csub(t0,t2); o3 = csub(t1,t3);
    }
    float2 w1o, w2o, w3o;
    if (!INV) {
        w1o = make_float2(C*(o1.x + o1.y), C*(o1.y - o1.x));
        w2o = make_float2(o2.y, -o2.x);
        w3o = make_float2(C*(o3.y - o3.x), C*(-(o3.x + o3.y)));
    } else {
        w1o = make_float2(C*(o1.x - o1.y), C*(o1.y + o1.x));
        w2o = make_float2(-o2.y, o2.x);
        w3o = make_float2(C*(-(o3.x + o3.y)), C*(o3.x - o3.y));
    }
    v[0] = cadd(e0, o0);  v[4] = csub(e0, o0);
    v[1] = cadd(e1, w1o); v[5] = csub(e1, w1o);
    v[2] = cadd(e2, w2o); v[6] = csub(e2, w2o);
    v[3] = cadd(e3, w3o); v[7] = csub(e3, w3o);
}

// ===================== prep kernel machinery (Stockham, as R4) ==============

template<int INV>
__device__ __forceinline__ void stage_store(float2 v[8], float2* __restrict__ sb,
                                            const float2* __restrict__ W,
                                            int u, int sshift) {
    bf8<INV>(v);
    const int s  = 1 << sshift;
    const int k1 = u & ~(s - 1);
    const int base = u + 7 * k1;
    float2 w1 = W[k1];
    if (INV) w1.y = -w1.y;
    const float2 w2 = cmul(w1, w1);
    const float2 w3 = cmul(w2, w1);
    const float2 w4 = cmul(w2, w2);
    const float2 w5 = cmul(w3, w2);
    const float2 w6 = cmul(w3, w3);
    const float2 w7 = cmul(w4, w3);
    sb[PIDX(base)]         = v[0];
    sb[PIDX(base + s)]     = cmul(v[1], w1);
    sb[PIDX(base + 2*s)]   = cmul(v[2], w2);
    sb[PIDX(base + 3*s)]   = cmul(v[3], w3);
    sb[PIDX(base + 4*s)]   = cmul(v[4], w4);
    sb[PIDX(base + 5*s)]   = cmul(v[5], w5);
    sb[PIDX(base + 6*s)]   = cmul(v[6], w6);
    sb[PIDX(base + 7*s)]   = cmul(v[7], w7);
}

__device__ __forceinline__ void stage_load(float2 v[8], const float2* __restrict__ sb, int tid) {
#pragma unroll
    for (int k = 0; k < 8; ++k) v[k] = sb[PIDX(tid + 512 * k)];
}

template<int INV, int PAR>
__device__ __forceinline__ void fft4096r8(float2 v[8], float2* b0, float2* b1,
                                          const float2* __restrict__ W, int tid) {
    float2* A = PAR ? b1 : b0;
    float2* B = PAR ? b0 : b1;
    stage_store<INV>(v, A, W, tid, 0);
    __syncthreads();
    stage_load(v, A, tid);
    stage_store<INV>(v, B, W, tid, 3);
    __syncthreads();
    stage_load(v, B, tid);
    stage_store<INV>(v, A, W, tid, 6);
    __syncthreads();
    stage_load(v, A, tid);
    bf8<INV>(v);
}

#define PREP_SMEM ((2 * NPAD + WSIZE) * (int)sizeof(float2))

__device__ __forceinline__ void fill_W(float2* W, int tid) {
    if (tid < WSIZE) {
        float s, c; sincospif((float)tid * (1.0f / 2048.0f), &s, &c);
        W[tid] = make_float2(c, -s);
    }
}

__global__ void __launch_bounds__(NT, 1) ldr_prep_kernel(const float* __restrict__ x,
                                                         const float* __restrict__ G,
                                                         const float* __restrict__ H)
{
    extern __shared__ float2 smem2[];
    float2* b0 = smem2;
    float2* b1 = smem2 + NPAD;
    float2* W  = smem2 + 2 * NPAD;
    const int tid = threadIdx.x;
    fill_W(W, tid);
    __syncthreads();

    const int bid = blockIdx.x;
    float2 v[8];
    if (bid < 64) {                       // Hf = fft(D * H)
        const float* h = H + bid * NN;
#pragma unroll
        for (int k = 0; k < 8; ++k) {
            const int n = tid + 512 * k;
            float s, c; sincospif((float)n * (1.0f / 4096.0f), &s, &c);
            const float val = h[n];
            v[k] = make_float2(val * c, val * s);
        }
        fft4096r8<0,0>(v, b0, b1, W, tid);
#pragma unroll
        for (int k = 0; k < 8; ++k) g_Hf[bid][tid + 512 * k] = v[k];
    } else if (bid < 128) {               // Gf = fft(G)
        const float* g = G + (bid - 64) * NN;
#pragma unroll
        for (int k = 0; k < 8; ++k) v[k] = make_float2(g[tid + 512 * k], 0.0f);
        fft4096r8<0,0>(v, b0, b1, W, tid);
#pragma unroll
        for (int k = 0; k < 8; ++k) g_Gf[bid - 64][tid + 512 * k] = v[k];
    } else {                              // Xf = ifft(conj(D) * x) (with 1/N)
        const float* xp = x + (bid - 128) * NN;
#pragma unroll
        for (int k = 0; k < 8; ++k) {
            const int n = tid + 512 * k;
            float s, c; sincospif((float)n * (1.0f / 4096.0f), &s, &c);
            const float val = xp[n];
            v[k] = make_float2(val * c, -val * s);
        }
        fft4096r8<1,0>(v, b0, b1, W, tid);
        const float inv = 1.0f / (float)NN;
#pragma unroll
        for (int k = 0; k < 8; ++k)
            g_Xf[bid - 128][tid + 512 * k] = make_float2(v[k].x * inv, v[k].y * inv);
    }
}

// ===================== main kernel: four-step FFT ===========================

// 8x8 Eklundh transpose among 8 lanes of a group (xor masks < 8 stay in-group).
__device__ __forceinline__ void transpose8(float2 t[8], int sub) {
#pragma unroll
    for (int d = 1; d < 8; d <<= 1) {
        const bool up = (sub & d) != 0;
#pragma unroll
        for (int mlow = 0; mlow < 8; ++mlow) {
            if (mlow & d) continue;
            const int mhigh = mlow | d;
            float2 send = up ? t[mlow] : t[mhigh];
            float2 recv;
            recv.x = __shfl_xor_sync(0xffffffffu, send.x, d, 32);
            recv.y = __shfl_xor_sync(0xffffffffu, send.y, d, 32);
            if (up) t[mlow] = recv; else t[mhigh] = recv;
        }
    }
}

// FFT4096, layout L -> L. One smem exchange + one barrier.
template<int INV, int PAR>
__device__ __forceinline__ void fftL(float2 v[8], float2* bufA, float2* bufB,
                                     const float2 tw64[8],
                                     float2 midA, float2 midStep,
                                     int P, int sub) {
    float2* buf = PAR ? bufB : bufA;
    // FFT64 #1 (over q = s + 8e)
    bf8<INV>(v);
#pragma unroll
    for (int m = 1; m < 8; ++m) {
        float2 w = tw64[m]; if (INV) w.y = -w.y;
        v[m] = cmul(v[m], w);
    }
    transpose8(v, sub);
    bf8<INV>(v);
    // mid twiddle W4096^{P*u}, u = sub + 8r
    {
        float2 tw = midA;     if (INV) tw.y = -tw.y;
        float2 st = midStep;  if (INV) st.y = -st.y;
#pragma unroll
        for (int r = 0; r < 8; ++r) {
            v[r] = cmul(v[r], tw);
            tw = cmul(tw, st);
        }
    }
    // block transpose: write (p=P, u), read (p = sub+8e, u-col = P)
    const int wb = TSTRIDE * P + sub;
#pragma unroll
    for (int r = 0; r < 8; ++r) buf[wb + 8 * r] = v[r];
    __syncthreads();
    const int rb = TSTRIDE * sub + P;
#pragma unroll
    for (int e = 0; e < 8; ++e) v[e] = buf[rb + 8 * TSTRIDE * e];
    // FFT64 #2 (over p)
    bf8<INV>(v);
#pragma unroll
    for (int m = 1; m < 8; ++m) {
        float2 w = tw64[m]; if (INV) w.y = -w.y;
        v[m] = cmul(v[m], w);
    }
    transpose8(v, sub);
    bf8<INV>(v);
    // out: reg r holds index P + 64*(sub + 8r)
}

// one packed chain (two terms sharing xf); buffers used: PAR, PAR^1, PAR.
template<int PAR>
__device__ __forceinline__ void do_chain(const float2* __restrict__ hf1,
                                         const float2* __restrict__ hf2,
                                         const float2* __restrict__ gf1,
                                         const float2* __restrict__ gf2,
                                         const float2* __restrict__ xf,
                                         float2* bufA, float2* bufB,
                                         const float2 tw64[8],
                                         float2 midA, float2 midStep, float2 d0,
                                         float2 acc[8], int P, int sub, int nbase)
{
    const float c8c[8] = {1.0f, 0.92387953251128675613f, 0.70710678118654752440f,
                          0.38268343236508977172f, 0.0f, -0.38268343236508977172f,
                          -0.70710678118654752440f, -0.92387953251128675613f};
    const float c8s[8] = {0.0f, 0.38268343236508977172f, 0.70710678118654752440f,
                          0.92387953251128675613f, 1.0f, 0.92387953251128675613f,
                          0.70710678118654752440f, 0.38268343236508977172f};
    float2 v[8];
#pragma unroll
    for (int k = 0; k < 8; ++k) {
        const int n = nbase + 512 * k;
        const float2 xv = xf[n];
        const float2 u1 = cmul(hf1[n], xv);
        const float2 u2 = cmul(hf2[n], xv);
        v[k] = make_float2(u1.x - u2.y, u1.y + u2.x);   // u1 + i*u2
    }
    fftL<0, PAR>(v, bufA, bufB, tw64, midA, midStep, P, sub);
    // D[k] = d0 * e^{i pi r/8}
#pragma unroll
    for (int r = 0; r < 8; ++r)
        v[r] = cmul(v[r], cmul(d0, make_float2(c8c[r], c8s[r])));
    fftL<0, PAR ^ 1>(v, bufA, bufB, tw64, midA, midStep, P, sub);

    // Hermitian unpack through buffer PAR: store W[n] at (p=P,u), read rev(n)
    float2* U = PAR ? bufB : bufA;
    const int wb = TSTRIDE * P + sub;
#pragma unroll
    for (int r = 0; r < 8; ++r) U[wb + 8 * r] = v[r];
    __syncthreads();
#pragma unroll
    for (int r = 0; r < 8; ++r) {
        const int n   = nbase + 512 * r;
        const int rev = (NN - n) & (NN - 1);
        const float2 ws = U[TSTRIDE * (rev & 63) + (rev >> 6)];
        const float2 t1 = make_float2(v[r].x + ws.x, v[r].y - ws.y);
        const float2 t2 = make_float2(v[r].y + ws.y, ws.x - v[r].x);
        acc[r] = cadd(acc[r], cadd(cmul(gf1[n], t1), cmul(gf2[n], t2)));
    }
}

__global__ void __launch_bounds__(NT, 1) ldr_main_kernel(float* __restrict__ out)
{
    extern __shared__ float2 smem2[];
    float2* bufA = smem2;
    float2* bufB = smem2 + TBUF;
    const int tid = threadIdx.x;
    const int w   = tid >> 5;
    const int l   = tid & 31;
    const int g   = l >> 3;
    const int sub = l & 7;
    const int P   = 4 * w + g;
    const int nbase = P + 64 * sub;       // global indices: nbase + 512*j

    // per-thread twiddle constants
    float2 tw64[8];
    tw64[0] = make_float2(1.0f, 0.0f);
    {
        float s, c; sincospif((float)sub * (1.0f / 32.0f), &s, &c);
        const float2 w1 = make_float2(c, -s);
        tw64[1] = w1;
#pragma unroll
        for (int m = 2; m < 8; ++m) tw64[m] = cmul(tw64[m-1], w1);
    }
    float2 midA, midStep, d0;
    { float s, c; sincospif((float)(P * sub) * (1.0f / 2048.0f), &s, &c); midA    = make_float2(c, -s); }
    { float s, c; sincospif((float)P * (1.0f / 256.0f), &s, &c);          midStep = make_float2(c, -s); }
    { float s, c; sincospif((float)nbase * (1.0f / 4096.0f), &s, &c);     d0      = make_float2(c,  s); }

    const int j = blockIdx.x >> 5;
    const int b = blockIdx.x & 31;

    float2 acc[8];
#pragma unroll
    for (int k = 0; k < 8; ++k) acc[k] = make_float2(0.0f, 0.0f);

    // 8 packed chains: chain c -> i = c>>1, sp = c&1, rows r1, r1+1
#pragma unroll 1
    for (int c = 0; c < 8; c += 2) {
        {
            const int i  = (c    ) >> 1, sp = (c    ) & 1;
            const int r1 = (i * COUT + j) * RANK + 2 * sp;
            do_chain<0>(g_Hf[r1], g_Hf[r1 + 1], g_Gf[r1], g_Gf[r1 + 1],
                        g_Xf[i * BATCH + b], bufA, bufB, tw64, midA, midStep, d0,
                        acc, P, sub, nbase);
        }
        {
            const int i  = (c + 1) >> 1, sp = (c + 1) & 1;
            const int r1 = (i * COUT + j) * RANK + 2 * sp;
            do_chain<1>(g_Hf[r1], g_Hf[r1 + 1], g_Gf[r1], g_Gf[r1 + 1],
                        g_Xf[i * BATCH + b], bufA, bufB, tw64, midA, midStep, d0,
                        acc, P, sub, nbase);
        }
    }

    // out = Re(ifft(acc)) / (2N)
    fftL<1, 0>(acc, bufA, bufB, tw64, midA, midStep, P, sub);
    float* op = out + (j * BATCH + b) * NN;
    const float inv = 1.0f / (2.0f * (float)NN);
#pragma unroll
    for (int r = 0; r < 8; ++r) op[nbase + 512 * r] = acc[r].x * inv;
}

extern "C" void kernel_launch(void* const* d_in, const int* in_sizes, int n_in,
                              void* d_out, int out_size)
{
    const float* x = (const float*)d_in[0];   // (4, 32, 4096)
    const float* G = (const float*)d_in[1];   // (4, 4, 4, 4096)
    const float* H = (const float*)d_in[2];   // (4, 4, 4, 4096)
    float* out = (float*)d_out;               // (4, 32, 4096)

    cudaFuncSetAttribute(ldr_prep_kernel, cudaFuncAttributeMaxDynamicSharedMemorySize, PREP_SMEM);
    cudaFuncSetAttribute(ldr_main_kernel, cudaFuncAttributeMaxDynamicSharedMemorySize, MAIN_SMEM);

    ldr_prep_kernel<<<256, NT, PREP_SMEM>>>(x, G, H);
    ldr_main_kernel<<<128, NT, MAIN_SMEM>>>(out);
}

// round 6
// speedup vs baseline: 1.5544x; 1.5544x over previous
#include <cuda_runtime.h>

// LDR toeplitz-displacement layer via FFT with 2-term real packing.
//   Hf = fft(D*H); Gf = fft(G); Xf = ifft(conj(D)*x)
//   t = D*fft(Hf.Xf) is REAL => pack two terms: z = u1 + i*u2,
//   W = fft(D.fft(z)) = Tf1 + i*Tf2 (Tf Hermitian), unpack via reversed read.
//   out = Re(ifft(sum Gf.Tf)) / (2N).
// MAIN FFT: radix-16 Stockham, NT=256, 16 pts/thread, coalesced layout
//   v[k] = data[tid + 256k]. Stages s=1, s=16 (smem), s=256 in regs.
//   => 2 exchanges + 2 barriers per FFT (information-theoretic min for r=16).
// PREP FFT: radix-8 Stockham (as R4), NT=512.

#define NN    4096
#define CIN   4
#define COUT  4
#define RANK  4
#define BATCH 32

// ---- prep kernel constants (radix-8, NT=512) ----
#define NTP   512
#define PIDX(i) ((i) + ((i) >> 3))
#define NPAD   4608
#define WSIZE  512

// ---- main kernel constants (radix-16, NT=256) ----
#define NTM   256
#define PIDX16(i) ((i) + ((i) >> 4))
#define NPAD16 4352          // 4096 + 256
#define W16SIZE 256
#define MAIN_SMEM ((2 * NPAD16 + W16SIZE) * (int)sizeof(float2))
#define PREP_SMEM ((2 * NPAD + WSIZE) * (int)sizeof(float2))

__device__ float2 g_Hf[CIN*COUT*RANK][NN];   // 2 MB
__device__ float2 g_Gf[CIN*COUT*RANK][NN];   // 2 MB
__device__ float2 g_Xf[CIN*BATCH][NN];       // 4 MB

__device__ __forceinline__ float2 cmul(float2 a, float2 b) {
    return make_float2(a.x*b.x - a.y*b.y, a.x*b.y + a.y*b.x);
}
__device__ __forceinline__ float2 cadd(float2 a, float2 b) { return make_float2(a.x+b.x, a.y+b.y); }
__device__ __forceinline__ float2 csub(float2 a, float2 b) { return make_float2(a.x-b.x, a.y-b.y); }

// ======================= prep: radix-8 Stockham (R4) ========================

template<int INV>
__device__ __forceinline__ void bf8(float2 v[8]) {
    const float C = 0.70710678118654752440f;
    float2 e0,e1,e2,e3,o0,o1,o2,o3;
    {
        float2 t0 = cadd(v[0], v[4]);
        float2 t1 = csub(v[0], v[4]);
        float2 t2 = cadd(v[2], v[6]);
        float2 d  = csub(v[2], v[6]);
        float2 t3 = INV ? make_float2(-d.y, d.x) : make_float2(d.y, -d.x);
        e0 = cadd(t0,t2); e1 = cadd(t1,t3); e2 = csub(t0,t2); e3 = csub(t1,t3);
    }
    {
        float2 t0 = cadd(v[1], v[5]);
        float2 t1 = csub(v[1], v[5]);
        float2 t2 = cadd(v[3], v[7]);
        float2 d  = csub(v[3], v[7]);
        float2 t3 = INV ? make_float2(-d.y, d.x) : make_float2(d.y, -d.x);
        o0 = cadd(t0,t2); o1 = cadd(t1,t3); o2 = csub(t0,t2); o3 = csub(t1,t3);
    }
    float2 w1o, w2o, w3o;
    if (!INV) {
        w1o = make_float2(C*(o1.x + o1.y), C*(o1.y - o1.x));
        w2o = make_float2(o2.y, -o2.x);
        w3o = make_float2(C*(o3.y - o3.x), C*(-(o3.x + o3.y)));
    } else {
        w1o = make_float2(C*(o1.x - o1.y), C*(o1.y + o1.x));
        w2o = make_float2(-o2.y, o2.x);
        w3o = make_float2(C*(-(o3.x + o3.y)), C*(o3.x - o3.y));
    }
    v[0] = cadd(e0, o0);  v[4] = csub(e0, o0);
    v[1] = cadd(e1, w1o); v[5] = csub(e1, w1o);
    v[2] = cadd(e2, w2o); v[6] = csub(e2, w2o);
    v[3] = cadd(e3, w3o); v[7] = csub(e3, w3o);
}

template<int INV>
__device__ __forceinline__ void stage_store8(float2 v[8], float2* __restrict__ sb,
                                             const float2* __restrict__ W,
                                             int u, int sshift) {
    bf8<INV>(v);
    const int s  = 1 << sshift;
    const int k1 = u & ~(s - 1);
    const int base = u + 7 * k1;
    float2 w1 = W[k1];
    if (INV) w1.y = -w1.y;
    const float2 w2 = cmul(w1, w1);
    const float2 w3 = cmul(w2, w1);
    const float2 w4 = cmul(w2, w2);
    const float2 w5 = cmul(w3, w2);
    const float2 w6 = cmul(w3, w3);
    const float2 w7 = cmul(w4, w3);
    sb[PIDX(base)]         = v[0];
    sb[PIDX(base + s)]     = cmul(v[1], w1);
    sb[PIDX(base + 2*s)]   = cmul(v[2], w2);
    sb[PIDX(base + 3*s)]   = cmul(v[3], w3);
    sb[PIDX(base + 4*s)]   = cmul(v[4], w4);
    sb[PIDX(base + 5*s)]   = cmul(v[5], w5);
    sb[PIDX(base + 6*s)]   = cmul(v[6], w6);
    sb[PIDX(base + 7*s)]   = cmul(v[7], w7);
}

__device__ __forceinline__ void stage_load8(float2 v[8], const float2* __restrict__ sb, int tid) {
#pragma unroll
    for (int k = 0; k < 8; ++k) v[k] = sb[PIDX(tid + 512 * k)];
}

template<int INV, int PAR>
__device__ __forceinline__ void fft4096r8(float2 v[8], float2* b0, float2* b1,
                                          const float2* __restrict__ W, int tid) {
    float2* A = PAR ? b1 : b0;
    float2* B = PAR ? b0 : b1;
    stage_store8<INV>(v, A, W, tid, 0);
    __syncthreads();
    stage_load8(v, A, tid);
    stage_store8<INV>(v, B, W, tid, 3);
    __syncthreads();
    stage_load8(v, B, tid);
    stage_store8<INV>(v, A, W, tid, 6);
    __syncthreads();
    stage_load8(v, A, tid);
    bf8<INV>(v);
}

__global__ void __launch_bounds__(NTP, 1) ldr_prep_kernel(const float* __restrict__ x,
                                                          const float* __restrict__ G,
                                                          const float* __restrict__ H)
{
    extern __shared__ float2 smem2[];
    float2* b0 = smem2;
    float2* b1 = smem2 + NPAD;
    float2* W  = smem2 + 2 * NPAD;
    const int tid = threadIdx.x;
    if (tid < WSIZE) {
        float s, c; sincospif((float)tid * (1.0f / 2048.0f), &s, &c);
        W[tid] = make_float2(c, -s);
    }
    __syncthreads();

    const int bid = blockIdx.x;
    float2 v[8];
    if (bid < 64) {                       // Hf = fft(D * H)
        const float* h = H + bid * NN;
#pragma unroll
        for (int k = 0; k < 8; ++k) {
            const int n = tid + 512 * k;
            float s, c; sincospif((float)n * (1.0f / 4096.0f), &s, &c);
            const float val = h[n];
            v[k] = make_float2(val * c, val * s);
        }
        fft4096r8<0,0>(v, b0, b1, W, tid);
#pragma unroll
        for (int k = 0; k < 8; ++k) g_Hf[bid][tid + 512 * k] = v[k];
    } else if (bid < 128) {               // Gf = fft(G)
        const float* g = G + (bid - 64) * NN;
#pragma unroll
        for (int k = 0; k < 8; ++k) v[k] = make_float2(g[tid + 512 * k], 0.0f);
        fft4096r8<0,0>(v, b0, b1, W, tid);
#pragma unroll
        for (int k = 0; k < 8; ++k) g_Gf[bid - 64][tid + 512 * k] = v[k];
    } else {                              // Xf = ifft(conj(D) * x) (with 1/N)
        const float* xp = x + (bid - 128) * NN;
#pragma unroll
        for (int k = 0; k < 8; ++k) {
            const int n = tid + 512 * k;
            float s, c; sincospif((float)n * (1.0f / 4096.0f), &s, &c);
            const float val = xp[n];
            v[k] = make_float2(val * c, -val * s);
        }
        fft4096r8<1,0>(v, b0, b1, W, tid);
        const float inv = 1.0f / (float)NN;
#pragma unroll
        for (int k = 0; k < 8; ++k)
            g_Xf[bid - 128][tid + 512 * k] = make_float2(v[k].x * inv, v[k].y * inv);
    }
}

// ======================= main: radix-16 Stockham ============================

// natural-order 16-pt DFT in registers (DIT 4x4)
template<int INV>
__device__ __forceinline__ void dft16(float2 v[16]) {
    // inner DFT4 over n1 (stride-4 quartets), result A[n0][k0] at v[n0+4k0]
#pragma unroll
    for (int n0 = 0; n0 < 4; ++n0) {
        float2 a = v[n0], b = v[n0+4], c = v[n0+8], d = v[n0+12];
        float2 t0 = cadd(a,c), t1 = csub(a,c), t2 = cadd(b,d), bd = csub(b,d);
        float2 t3 = INV ? make_float2(-bd.y, bd.x) : make_float2(bd.y, -bd.x);
        v[n0]    = cadd(t0,t2);
        v[n0+4]  = cadd(t1,t3);
        v[n0+8]  = csub(t0,t2);
        v[n0+12] = csub(t1,t3);
    }
    // twiddle W16^{n0*k0}  (fwd = (c, -s); inv = (c, s))
    const float C1 = 0.92387953251128675613f;   // cos pi/8
    const float S1 = 0.38268343236508977172f;   // sin pi/8
    const float CC = 0.70710678118654752440f;
#define TW16(idx, c, s) v[idx] = cmul(v[idx], make_float2((c), INV ? (s) : -(s)))
    TW16(1+4,  C1,  S1);   // W^1
    TW16(1+8,  CC,  CC);   // W^2
    TW16(1+12, S1,  C1);   // W^3
    TW16(2+4,  CC,  CC);   // W^2
    TW16(2+8,  0.0f, 1.0f);// W^4
    TW16(2+12, -CC, CC);   // W^6
    TW16(3+4,  S1,  C1);   // W^3
    TW16(3+8,  -CC, CC);   // W^6
    TW16(3+12, -C1, -S1);  // W^9
#undef TW16
    // outer DFT4 over n0 (consecutive quartets), X[k0+4k1]
    float2 t[16];
#pragma unroll
    for (int k0 = 0; k0 < 4; ++k0) {
        float2 a = v[4*k0], b = v[4*k0+1], c = v[4*k0+2], d = v[4*k0+3];
        float2 t0 = cadd(a,c), t1 = csub(a,c), t2 = cadd(b,d), bd = csub(b,d);
        float2 t3 = INV ? make_float2(-bd.y, bd.x) : make_float2(bd.y, -bd.x);
        t[k0]    = cadd(t0,t2);
        t[k0+4]  = cadd(t1,t3);
        t[k0+8]  = csub(t0,t2);
        t[k0+12] = csub(t1,t3);
    }
#pragma unroll
    for (int k = 0; k < 16; ++k) v[k] = t[k];
}

template<int INV>
__device__ __forceinline__ void stage_store16(float2 v[16], float2* __restrict__ sb,
                                              const float2* __restrict__ W,
                                              int u, int sshift) {
    dft16<INV>(v);
    const int s  = 1 << sshift;
    const int k1 = u & ~(s - 1);
    const int base = u + 15 * k1;
    float2 w1 = W[k1];
    if (INV) w1.y = -w1.y;
    float2 wp2 = cmul(w1, w1);
    float2 wp4 = cmul(wp2, wp2);
    float2 wp8 = cmul(wp4, wp4);
    float2 wp3 = cmul(w1, wp2);
    float2 wp5 = cmul(w1, wp4);
    float2 wp6 = cmul(wp2, wp4);
    float2 wp7 = cmul(wp3, wp4);
    sb[PIDX16(base)]        = v[0];
    sb[PIDX16(base +  1*s)] = cmul(v[1],  w1);
    sb[PIDX16(base +  2*s)] = cmul(v[2],  wp2);
    sb[PIDX16(base +  3*s)] = cmul(v[3],  wp3);
    sb[PIDX16(base +  4*s)] = cmul(v[4],  wp4);
    sb[PIDX16(base +  5*s)] = cmul(v[5],  wp5);
    sb[PIDX16(base +  6*s)] = cmul(v[6],  wp6);
    sb[PIDX16(base +  7*s)] = cmul(v[7],  wp7);
    sb[PIDX16(base +  8*s)] = cmul(v[8],  wp8);
    sb[PIDX16(base +  9*s)] = cmul(v[9],  cmul(wp8, w1));
    sb[PIDX16(base + 10*s)] = cmul(v[10], cmul(wp8, wp2));
    sb[PIDX16(base + 11*s)] = cmul(v[11], cmul(wp8, wp3));
    sb[PIDX16(base + 12*s)] = cmul(v[12], cmul(wp8, wp4));
    sb[PIDX16(base + 13*s)] = cmul(v[13], cmul(wp8, wp5));
    sb[PIDX16(base + 14*s)] = cmul(v[14], cmul(wp8, wp6));
    sb[PIDX16(base + 15*s)] = cmul(v[15], cmul(wp8, wp7));
}

__device__ __forceinline__ void stage_load16(float2 v[16], const float2* __restrict__ sb, int tid) {
#pragma unroll
    for (int k = 0; k < 16; ++k) v[k] = sb[PIDX16(tid + 256 * k)];
}

// stores go to buffers (PAR, PAR^1); in/out layout v[k] = data[tid + 256k]
template<int INV, int PAR>
__device__ __forceinline__ void fft4096r16(float2 v[16], float2* b0, float2* b1,
                                           const float2* __restrict__ W, int tid) {
    float2* A = PAR ? b1 : b0;
    float2* B = PAR ? b0 : b1;
    stage_store16<INV>(v, A, W, tid, 0);    // s = 1
    __syncthreads();
    stage_load16(v, A, tid);
    stage_store16<INV>(v, B, W, tid, 4);    // s = 16
    __syncthreads();
    stage_load16(v, B, tid);
    dft16<INV>(v);                          // s = 256: k1 = 0, in regs
}

// one packed chain (two terms sharing xf). Buffer discipline:
//   fft1<PAR>: stores (PAR, PAR^1); fft2<PAR>: stores (PAR, PAR^1);
//   unpack store -> buffer PAR. Callers alternate PAR per chain.
template<int PAR>
__device__ __forceinline__ void do_chain(const float2* __restrict__ hf1,
                                         const float2* __restrict__ hf2,
                                         const float2* __restrict__ gf1,
                                         const float2* __restrict__ gf2,
                                         const float2* __restrict__ xf,
                                         float2* b0, float2* b1,
                                         const float2* __restrict__ W,
                                         float2 d0, float2 acc[16], int tid)
{
    // e^{i*pi*k/16}, k = 0..15
    const float e16c[16] = { 1.0f, 0.98078528040323044913f, 0.92387953251128675613f,
        0.83146961230254523708f, 0.70710678118654752440f, 0.55557023301960222474f,
        0.38268343236508977172f, 0.19509032201612826785f, 0.0f, -0.19509032201612826785f,
        -0.38268343236508977172f, -0.55557023301960222474f, -0.70710678118654752440f,
        -0.83146961230254523708f, -0.92387953251128675613f, -0.98078528040323044913f };
    const float e16s[16] = { 0.0f, 0.19509032201612826785f, 0.38268343236508977172f,
        0.55557023301960222474f, 0.70710678118654752440f, 0.83146961230254523708f,
        0.92387953251128675613f, 0.98078528040323044913f, 1.0f, 0.98078528040323044913f,
        0.92387953251128675613f, 0.83146961230254523708f, 0.70710678118654752440f,
        0.55557023301960222474f, 0.38268343236508977172f, 0.19509032201612826785f };

    float2 v[16];
#pragma unroll
    for (int k = 0; k < 16; ++k) {
        const int n = tid + 256 * k;
        const float2 xv = xf[n];
        const float2 u1 = cmul(hf1[n], xv);
        const float2 u2 = cmul(hf2[n], xv);
        v[k] = make_float2(u1.x - u2.y, u1.y + u2.x);   // u1 + i*u2
    }
    fft4096r16<0, PAR>(v, b0, b1, W, tid);
    // D[n] = e^{i pi tid/4096} * e^{i pi k/16}
#pragma unroll
    for (int k = 0; k < 16; ++k)
        v[k] = cmul(v[k], cmul(d0, make_float2(e16c[k], e16s[k])));
    fft4096r16<0, PAR>(v, b0, b1, W, tid);

    // Hermitian unpack through buffer PAR (its last readers were pre-barrier)
    float2* U = PAR ? b1 : b0;
#pragma unroll
    for (int k = 0; k < 16; ++k) U[PIDX16(tid + 256 * k)] = v[k];
    __syncthreads();
#pragma unroll
    for (int k = 0; k < 16; ++k) {
        const int n   = tid + 256 * k;
        const int rev = (NN - n) & (NN - 1);
        const float2 ws = U[PIDX16(rev)];
        // Tf1' = v + conj(ws); Tf2' = -i*(v - conj(ws))  (x2 folded into scale)
        const float2 t1 = make_float2(v[k].x + ws.x, v[k].y - ws.y);
        const float2 t2 = make_float2(v[k].y + ws.y, ws.x - v[k].x);
        acc[k] = cadd(acc[k], cadd(cmul(gf1[n], t1), cmul(gf2[n], t2)));
    }
}

__global__ void __launch_bounds__(NTM, 1) ldr_main_kernel(float* __restrict__ out)
{
    extern __shared__ float2 smem2[];
    float2* b0 = smem2;
    float2* b1 = smem2 + NPAD16;
    float2* W  = smem2 + 2 * NPAD16;
    const int tid = threadIdx.x;
    {   // W[k1] = W4096^{k1}, k1 < 256
        float s, c; sincospif((float)tid * (1.0f / 2048.0f), &s, &c);
        W[tid] = make_float2(c, -s);
    }
    float2 d0;
    { float s, c; sincospif((float)tid * (1.0f / 4096.0f), &s, &c); d0 = make_float2(c, s); }
    __syncthreads();

    const int j = blockIdx.x >> 5;
    const int b = blockIdx.x & 31;

    float2 acc[16];
#pragma unroll
    for (int k = 0; k < 16; ++k) acc[k] = make_float2(0.0f, 0.0f);

    // 8 packed chains: chain c -> i = c>>1, sp = c&1; PAR alternates 0,1,...
#pragma unroll 1
    for (int c = 0; c < 8; c += 2) {
        {
            const int i  = (c    ) >> 1, sp = (c    ) & 1;
            const int r1 = (i * COUT + j) * RANK + 2 * sp;
            do_chain<0>(g_Hf[r1], g_Hf[r1 + 1], g_Gf[r1], g_Gf[r1 + 1],
                        g_Xf[i * BATCH + b], b0, b1, W, d0, acc, tid);
        }
        {
            const int i  = (c + 1) >> 1, sp = (c + 1) & 1;
            const int r1 = (i * COUT + j) * RANK + 2 * sp;
            do_chain<1>(g_Hf[r1], g_Hf[r1 + 1], g_Gf[r1], g_Gf[r1 + 1],
                        g_Xf[i * BATCH + b], b0, b1, W, d0, acc, tid);
        }
    }

    // out = Re(ifft(acc)) / (2N). Last chain (PAR=1) ended reading b1; fft<.,0>
    // stores b0 first whose last readers are pre-barrier => safe.
    fft4096r16<1, 0>(acc, b0, b1, W, tid);
    float* op = out + (j * BATCH + b) * NN;
    const float inv = 1.0f / (2.0f * (float)NN);
#pragma unroll
    for (int k = 0; k < 16; ++k) op[tid + 256 * k] = acc[k].x * inv;
}

extern "C" void kernel_launch(void* const* d_in, const int* in_sizes, int n_in,
                              void* d_out, int out_size)
{
    const float* x = (const float*)d_in[0];   // (4, 32, 4096)
    const float* G = (const float*)d_in[1];   // (4, 4, 4, 4096)
    const float* H = (const float*)d_in[2];   // (4, 4, 4, 4096)
    float* out = (float*)d_out;               // (4, 32, 4096)

    cudaFuncSetAttribute(ldr_prep_kernel, cudaFuncAttributeMaxDynamicSharedMemorySize, PREP_SMEM);
    cudaFuncSetAttribute(ldr_main_kernel, cudaFuncAttributeMaxDynamicSharedMemorySize, MAIN_SMEM);

    ldr_prep_kernel<<<256, NTP, PREP_SMEM>>>(x, G, H);
    ldr_main_kernel<<<128, NTM, MAIN_SMEM>>>(out);
}